// round 4
// baseline (speedup 1.0000x reference)
#include <cuda_runtime.h>
#include <cfloat>

#define BB   4
#define QN   256
#define KN   1024
#define DD   256     // input feature dim (q/k/v size)
#define HH   128     // hidden dim
#define NEGV -1000000.0f

// Scratch (alloc-free rule: __device__ globals)
__device__ float g_qproj[BB * QN * HH];   // 512 KB
__device__ float g_kproj[BB * KN * HH];   // 2 MB

// Accurate tanh via ex2: abs err ~1e-7 (MUFU.EX2 + MUFU.RCP are ~2^-22 accurate)
__device__ __forceinline__ float tanh_acc(float x) {
    float ax = fabsf(x);
    float e  = __expf(-2.0f * ax);                 // MUFU.EX2 path
    float r  = __fdividef(1.0f - e, 1.0f + e);     // MUFU.RCP path
    return copysignf(r, x);
}

// ---------------------------------------------------------------------------
// Fused projections: Y[r][h] = sum_i X[r][i] * W[h][i]   (torch Linear: X@W^T)
// blocks [0,64)   : queries -> g_qproj   (4*256 rows)
// blocks [64,320) : keys    -> g_kproj   (4*1024 rows)
// Block: 256 threads, 16 rows per block, full H=128.
// ---------------------------------------------------------------------------
__global__ __launch_bounds__(256)
void proj_kernel(const float* __restrict__ Xq, const float* __restrict__ Wq,
                 const float* __restrict__ Xk, const float* __restrict__ Wk)
{
    __shared__ float Xs[16 * 256];     // 16 KB
    __shared__ float Ws[128 * 33];     // ~16.9 KB, pad 33 -> conflict-free

    const bool isQ = (blockIdx.x < (BB * QN) / 16);
    const float* X = isQ ? Xq : Xk;
    const float* W = isQ ? Wq : Wk;
    float*       Y = isQ ? g_qproj : g_kproj;
    const int r0 = (isQ ? blockIdx.x : (blockIdx.x - (BB * QN) / 16)) * 16;
    const int t  = threadIdx.x;

    // stage 16 input rows (coalesced float4)
    const float4* xsrc = (const float4*)(X + (size_t)r0 * DD);
    #pragma unroll
    for (int n = 0; n < 4; ++n) {
        int j = t + 256 * n;           // 1024 float4 total
        ((float4*)Xs)[j] = xsrc[j];
    }

    const int h    = t & 127;          // warp-uniform rsub, lanes h consecutive
    const int rsub = t >> 7;
    float acc[8];
    #pragma unroll
    for (int j = 0; j < 8; ++j) acc[j] = 0.0f;

    for (int c = 0; c < 8; ++c) {      // 8 chunks of 32 along i
        __syncthreads();
        #pragma unroll
        for (int n = 0; n < 16; ++n) { // stage W[:, c*32 .. +32)
            int idx = t + 256 * n;     // 0..4095
            int hh  = idx >> 5, ii = idx & 31;
            Ws[hh * 33 + ii] = W[hh * 256 + c * 32 + ii];
        }
        __syncthreads();
        #pragma unroll
        for (int i = 0; i < 32; ++i) {
            float wv = Ws[h * 33 + i];             // conflict-free (stride 33)
            #pragma unroll
            for (int j = 0; j < 8; ++j)            // Xs reads: warp-broadcast
                acc[j] += wv * Xs[(rsub * 8 + j) * 256 + c * 32 + i];
        }
    }
    #pragma unroll
    for (int j = 0; j < 8; ++j)
        Y[(size_t)(r0 + rsub * 8 + j) * HH + h] = acc[j];   // coalesced
}

// ---------------------------------------------------------------------------
// Fused: scores (tanh feature dot) -> masked softmax -> attn @ V
// Block = (b, pair of q rows). Grid = 4 * 128 = 512 blocks, 256 threads.
// k-proj staged in 64x128 XOR-swizzled smem tiles; tiles beyond valid skipped.
// ---------------------------------------------------------------------------
__global__ __launch_bounds__(256)
void attn_kernel(const float* __restrict__ values,
                 const int*   __restrict__ valid_lens,
                 const float* __restrict__ w_v,
                 float*       __restrict__ out)
{
    __shared__ float s_kv[64 * 128];       // 32 KB swizzled k-proj tile (reused for AV reduce)
    __shared__ float s_sc[2][KN];          // 8 KB scores -> exp weights
    __shared__ float s_q[2 * 128];         // 1 KB
    __shared__ float s_w[128];
    __shared__ float s_part[2][64][2];     // h-split partials
    __shared__ float s_red[8];
    __shared__ float s_red2[8];
    __shared__ float s_inv[2];

    const int t  = threadIdx.x;
    const int b  = blockIdx.x >> 7;
    const int qg = blockIdx.x & 127;
    const int q0 = qg * 2;
    const int valid = valid_lens[b];

    if (t < 128) s_w[t] = w_v[t];
    s_q[t] = g_qproj[(size_t)(b * QN + q0) * HH + t];   // 256 floats
    __syncthreads();

    const int k    = t & 63;          // warp-uniform qi/half; lanes k consecutive
    const int qi   = (t >> 6) & 1;
    const int half = t >> 7;

    const float4* q4 = (const float4*)(s_q + qi * 128 + half * 64);
    const float4* w4 = (const float4*)(s_w + half * 64);
    const float*  kbase = g_kproj + (size_t)b * KN * HH;

    const int ntiles = (valid + 63) >> 6;

    for (int tile = 0; tile < ntiles; ++tile) {
        // stage tile: 64 rows x 128 floats, XOR-swizzled for conflict-free LDS.128
        const float4* src = (const float4*)(kbase + (size_t)tile * 64 * HH);
        #pragma unroll
        for (int n = 0; n < 8; ++n) {
            int j   = t + 256 * n;           // 2048 float4
            int row = j >> 5;
            int c4  = j & 31;
            ((float4*)s_kv)[row * 32 + (c4 ^ (row & 7))] = src[j];
        }
        __syncthreads();

        float acc = 0.0f;
        #pragma unroll
        for (int h4 = 0; h4 < 16; ++h4) {
            int c4 = half * 16 + h4;
            float4 kv = ((const float4*)s_kv)[k * 32 + (c4 ^ (k & 7))];
            float4 qv = q4[h4];
            float4 wv = w4[h4];
            acc += wv.x * tanh_acc(qv.x + kv.x);
            acc += wv.y * tanh_acc(qv.y + kv.y);
            acc += wv.z * tanh_acc(qv.z + kv.z);
            acc += wv.w * tanh_acc(qv.w + kv.w);
        }
        s_part[qi][k][half] = acc;
        __syncthreads();
        if (t < 128) {
            int kk = t & 63, qq = t >> 6;
            float s = s_part[qq][kk][0] + s_part[qq][kk][1];
            int kg = tile * 64 + kk;
            s_sc[qq][kg] = (kg < valid) ? s : NEGV;
        }
        __syncthreads();
    }
    // fill masked tail
    for (int idx = t + ntiles * 64; idx < KN; idx += 256) {
        s_sc[0][idx] = NEGV;
        s_sc[1][idx] = NEGV;
    }
    __syncthreads();

    // ---- masked softmax (unnormalized exp; 1/sum folded into epilogue) ----
    const int qi2 = t >> 7, sub = t & 127;
    float mx = -FLT_MAX;
    #pragma unroll
    for (int j = 0; j < 8; ++j)
        mx = fmaxf(mx, s_sc[qi2][sub + 128 * j]);
    #pragma unroll
    for (int o = 16; o; o >>= 1)
        mx = fmaxf(mx, __shfl_xor_sync(0xffffffffu, mx, o));
    const int w = t >> 5;
    if ((t & 31) == 0) s_red[w] = mx;
    __syncthreads();
    const float rm = fmaxf(fmaxf(s_red[qi2 * 4 + 0], s_red[qi2 * 4 + 1]),
                           fmaxf(s_red[qi2 * 4 + 2], s_red[qi2 * 4 + 3]));

    float lsum = 0.0f;
    #pragma unroll
    for (int j = 0; j < 8; ++j) {
        int idx = sub + 128 * j;
        float e = __expf(s_sc[qi2][idx] - rm);   // masked -> exp(-1e6) == 0
        s_sc[qi2][idx] = e;
        lsum += e;
    }
    #pragma unroll
    for (int o = 16; o; o >>= 1)
        lsum += __shfl_xor_sync(0xffffffffu, lsum, o);
    if ((t & 31) == 0) s_red2[w] = lsum;
    __syncthreads();
    if (t < 2)
        s_inv[t] = 1.0f / (s_red2[t * 4] + s_red2[t * 4 + 1] +
                           s_red2[t * 4 + 2] + s_red2[t * 4 + 3]);
    __syncthreads();

    // ---- attn @ V: thread = (v4 = t&63, ksub = t>>6), 4-way k-split ----
    const int v4   = t & 63;
    const int ksub = t >> 6;
    float4 a0 = {0, 0, 0, 0}, a1 = {0, 0, 0, 0};
    const float4* vb = (const float4*)(values + (size_t)b * KN * DD) + v4;
    for (int kk = ksub; kk < valid; kk += 4) {
        float4 vv = vb[kk * 64];                 // coalesced 512B per warp
        float p0 = s_sc[0][kk];                  // broadcast LDS
        float p1 = s_sc[1][kk];
        a0.x += p0 * vv.x; a0.y += p0 * vv.y; a0.z += p0 * vv.z; a0.w += p0 * vv.w;
        a1.x += p1 * vv.x; a1.y += p1 * vv.y; a1.z += p1 * vv.z; a1.w += p1 * vv.w;
    }
    float* s_av = s_kv;                          // reuse (8 KB needed)
    ((float4*)s_av)[(ksub * 2 + 0) * 64 + v4] = a0;
    ((float4*)s_av)[(ksub * 2 + 1) * 64 + v4] = a1;
    __syncthreads();
    if (t < 128) {
        int qq = t >> 6, vv4 = t & 63;
        float4 s = {0, 0, 0, 0};
        #pragma unroll
        for (int ks = 0; ks < 4; ++ks) {
            float4 p = ((const float4*)s_av)[(ks * 2 + qq) * 64 + vv4];
            s.x += p.x; s.y += p.y; s.z += p.z; s.w += p.w;
        }
        float inv = s_inv[qq];
        float4 o = {s.x * inv, s.y * inv, s.z * inv, s.w * inv};
        ((float4*)(out + (size_t)(b * QN + q0 + qq) * DD))[vv4] = o;
    }
}

// ---------------------------------------------------------------------------
extern "C" void kernel_launch(void* const* d_in, const int* in_sizes, int n_in,
                              void* d_out, int out_size)
{
    const float* queries    = (const float*)d_in[0];   // [4,256,256]
    const float* keys       = (const float*)d_in[1];   // [4,1024,256]
    const float* values     = (const float*)d_in[2];   // [4,1024,256]
    const int*   valid_lens = (const int*)  d_in[3];   // [4]
    const float* W_q        = (const float*)d_in[4];   // [128,256]
    const float* W_k        = (const float*)d_in[5];   // [128,256]
    const float* w_v        = (const float*)d_in[6];   // [128]
    float* out = (float*)d_out;                        // [4,256,256]

    proj_kernel<<< (BB * QN) / 16 + (BB * KN) / 16, 256 >>>(queries, W_q, keys, W_k);
    attn_kernel<<< BB * (QN / 2), 256 >>>(values, valid_lens, w_v, out);
}

// round 10
// speedup vs baseline: 1.2636x; 1.2636x over previous
#include <cuda_runtime.h>
#include <cfloat>

#define BB   4
#define QN   256
#define KN   1024
#define DD   256     // input feature dim (q/k/v size)
#define HH   128     // hidden dim
#define NEGV -1000000.0f
#define RPB  32      // rows per proj block

// Scratch (alloc-free rule: __device__ globals; zero-init at module load)
__device__ float g_qproj[BB * QN * HH];   // 512 KB
__device__ float g_kproj[BB * KN * HH];   // 2 MB

// Hardware tanh (MUFU.TANH): 1 MUFU op, abs err ~1e-4-class.
// Measured baseline rel_err was 3.1e-7 with accurate tanh -> ample headroom vs 1e-3.
__device__ __forceinline__ float tanh_fast(float x) {
    float y;
    asm("tanh.approx.f32 %0, %1;" : "=f"(y) : "f"(x));
    return y;
}

// ---------------------------------------------------------------------------
// Fused projections: Y[r][h] = sum_i X[r][i] * W[h][i]   (torch Linear: X@W^T)
// blocks [0,32)    : queries -> g_qproj   (4*256 rows)
// blocks [32,160)  : keys    -> g_kproj   (4*1024 rows); blocks entirely
//                    beyond valid_lens[b] exit early (rows never consumed).
// Block: 256 threads, 32 rows, full H=128.
// ---------------------------------------------------------------------------
__global__ __launch_bounds__(256)
void proj_kernel(const float* __restrict__ Xq, const float* __restrict__ Wq,
                 const float* __restrict__ Xk, const float* __restrict__ Wk,
                 const int*   __restrict__ valid_lens)
{
    __shared__ float Xs[RPB * 256];    // 32 KB
    __shared__ float Ws[128 * 33];     // ~16.9 KB, pad 33 -> conflict-free

    const bool isQ = (blockIdx.x < (BB * QN) / RPB);
    const float* X = isQ ? Xq : Xk;
    const float* W = isQ ? Wq : Wk;
    float*       Y = isQ ? g_qproj : g_kproj;
    const int r0 = (isQ ? blockIdx.x : (blockIdx.x - (BB * QN) / RPB)) * RPB;

    if (!isQ) {
        int b    = r0 / KN;            // RPB divides KN -> block within one b
        int kloc = r0 - b * KN;
        if (kloc >= valid_lens[b]) return;   // rows never read by attn
    }
    const int t = threadIdx.x;

    // stage 32 input rows (coalesced float4)
    const float4* xsrc = (const float4*)(X + (size_t)r0 * DD);
    #pragma unroll
    for (int n = 0; n < 8; ++n) {
        int j = t + 256 * n;           // 2048 float4 total
        ((float4*)Xs)[j] = xsrc[j];
    }

    const int h    = t & 127;          // lanes: h consecutive; rsub warp-uniform
    const int rsub = t >> 7;           // 0/1 -> 16 rows each
    float acc[16];
    #pragma unroll
    for (int j = 0; j < 16; ++j) acc[j] = 0.0f;

    for (int c = 0; c < 8; ++c) {      // 8 chunks of 32 along i
        __syncthreads();
        #pragma unroll
        for (int n = 0; n < 16; ++n) { // stage W[:, c*32 .. +32)
            int idx = t + 256 * n;     // 0..4095
            int hh  = idx >> 5, ii = idx & 31;
            Ws[hh * 33 + ii] = W[hh * 256 + c * 32 + ii];   // coalesced in
        }
        __syncthreads();
        #pragma unroll
        for (int i4 = 0; i4 < 8; ++i4) {
            float w0 = Ws[h * 33 + i4 * 4 + 0];    // conflict-free (stride 33)
            float w1 = Ws[h * 33 + i4 * 4 + 1];
            float w2 = Ws[h * 33 + i4 * 4 + 2];
            float w3 = Ws[h * 33 + i4 * 4 + 3];
            #pragma unroll
            for (int j = 0; j < 16; ++j) {         // Xs: warp-broadcast LDS.128
                float4 x4 = *(const float4*)&Xs[(rsub * 16 + j) * 256 + c * 32 + i4 * 4];
                acc[j] = fmaf(w0, x4.x, acc[j]);
                acc[j] = fmaf(w1, x4.y, acc[j]);
                acc[j] = fmaf(w2, x4.z, acc[j]);
                acc[j] = fmaf(w3, x4.w, acc[j]);
            }
        }
    }
    #pragma unroll
    for (int j = 0; j < 16; ++j)
        Y[(size_t)(r0 + rsub * 16 + j) * HH + h] = acc[j];   // coalesced
}

// ---------------------------------------------------------------------------
// Fused: scores (tanh feature dot) -> masked softmax -> attn @ V
// Block = (b, pair of q rows). Grid = 4 * 128 = 512 blocks, 256 threads.
// k-proj staged in 64x128 XOR-swizzled smem tiles; tiles beyond valid skipped.
// ---------------------------------------------------------------------------
__global__ __launch_bounds__(256)
void attn_kernel(const float* __restrict__ values,
                 const int*   __restrict__ valid_lens,
                 const float* __restrict__ w_v,
                 float*       __restrict__ out)
{
    __shared__ float s_kv[64 * 128];       // 32 KB swizzled k-proj tile (reused for AV reduce)
    __shared__ float s_sc[2][KN];          // 8 KB scores -> exp weights
    __shared__ float s_q[2 * 128];         // 1 KB
    __shared__ float s_w[128];
    __shared__ float s_part[2][64][2];     // h-split partials
    __shared__ float s_red[8];
    __shared__ float s_red2[8];
    __shared__ float s_inv[2];

    const int t  = threadIdx.x;
    const int b  = blockIdx.x >> 7;
    const int qg = blockIdx.x & 127;
    const int q0 = qg * 2;
    const int valid = valid_lens[b];

    if (t < 128) s_w[t] = w_v[t];
    s_q[t] = g_qproj[(size_t)(b * QN + q0) * HH + t];   // 256 floats
    __syncthreads();

    const int k    = t & 63;          // warp-uniform qi/half; lanes k consecutive
    const int qi   = (t >> 6) & 1;
    const int half = t >> 7;

    const float4* q4 = (const float4*)(s_q + qi * 128 + half * 64);
    const float4* w4 = (const float4*)(s_w + half * 64);
    const float*  kbase = g_kproj + (size_t)b * KN * HH;

    const int ntiles = (valid + 63) >> 6;

    for (int tile = 0; tile < ntiles; ++tile) {
        // stage tile: 64 rows x 128 floats, XOR-swizzled for conflict-free LDS.128
        const float4* src = (const float4*)(kbase + (size_t)tile * 64 * HH);
        #pragma unroll
        for (int n = 0; n < 8; ++n) {
            int j   = t + 256 * n;           // 2048 float4
            int row = j >> 5;
            int c4  = j & 31;
            ((float4*)s_kv)[row * 32 + (c4 ^ (row & 7))] = src[j];
        }
        __syncthreads();

        float acc = 0.0f;
        #pragma unroll
        for (int h4 = 0; h4 < 16; ++h4) {
            int c4 = half * 16 + h4;
            float4 kv = ((const float4*)s_kv)[k * 32 + (c4 ^ (k & 7))];
            float4 qv = q4[h4];                       // broadcast LDS
            float4 wv = w4[h4];                       // broadcast LDS
            acc = fmaf(wv.x, tanh_fast(qv.x + kv.x), acc);
            acc = fmaf(wv.y, tanh_fast(qv.y + kv.y), acc);
            acc = fmaf(wv.z, tanh_fast(qv.z + kv.z), acc);
            acc = fmaf(wv.w, tanh_fast(qv.w + kv.w), acc);
        }
        s_part[qi][k][half] = acc;
        __syncthreads();
        if (t < 128) {
            int kk = t & 63, qq = t >> 6;
            float s = s_part[qq][kk][0] + s_part[qq][kk][1];
            int kg = tile * 64 + kk;
            s_sc[qq][kg] = (kg < valid) ? s : NEGV;   // masks any garbage rows
        }
        __syncthreads();
    }
    // fill masked tail
    for (int idx = t + ntiles * 64; idx < KN; idx += 256) {
        s_sc[0][idx] = NEGV;
        s_sc[1][idx] = NEGV;
    }
    __syncthreads();

    // ---- masked softmax (unnormalized exp; 1/sum folded into epilogue) ----
    const int qi2 = t >> 7, sub = t & 127;
    float mx = -FLT_MAX;
    #pragma unroll
    for (int j = 0; j < 8; ++j)
        mx = fmaxf(mx, s_sc[qi2][sub + 128 * j]);
    #pragma unroll
    for (int o = 16; o; o >>= 1)
        mx = fmaxf(mx, __shfl_xor_sync(0xffffffffu, mx, o));
    const int w = t >> 5;
    if ((t & 31) == 0) s_red[w] = mx;
    __syncthreads();
    const float rm = fmaxf(fmaxf(s_red[qi2 * 4 + 0], s_red[qi2 * 4 + 1]),
                           fmaxf(s_red[qi2 * 4 + 2], s_red[qi2 * 4 + 3]));

    float lsum = 0.0f;
    #pragma unroll
    for (int j = 0; j < 8; ++j) {
        int idx = sub + 128 * j;
        float e = __expf(s_sc[qi2][idx] - rm);   // masked -> exp(-1e6) == 0
        s_sc[qi2][idx] = e;
        lsum += e;
    }
    #pragma unroll
    for (int o = 16; o; o >>= 1)
        lsum += __shfl_xor_sync(0xffffffffu, lsum, o);
    if ((t & 31) == 0) s_red2[w] = lsum;
    __syncthreads();
    if (t < 2)
        s_inv[t] = 1.0f / (s_red2[t * 4] + s_red2[t * 4 + 1] +
                           s_red2[t * 4 + 2] + s_red2[t * 4 + 3]);
    __syncthreads();

    // ---- attn @ V: thread = (v4 = t&63, ksub = t>>6), 4-way k-split ----
    const int v4   = t & 63;
    const int ksub = t >> 6;
    float4 a0 = {0, 0, 0, 0}, a1 = {0, 0, 0, 0};
    const float4* vb = (const float4*)(values + (size_t)b * KN * DD) + v4;
    for (int kk = ksub; kk < valid; kk += 4) {
        float4 vv = vb[kk * 64];                 // coalesced 512B per warp
        float p0 = s_sc[0][kk];                  // broadcast LDS
        float p1 = s_sc[1][kk];
        a0.x += p0 * vv.x; a0.y += p0 * vv.y; a0.z += p0 * vv.z; a0.w += p0 * vv.w;
        a1.x += p1 * vv.x; a1.y += p1 * vv.y; a1.z += p1 * vv.z; a1.w += p1 * vv.w;
    }
    float* s_av = s_kv;                          // reuse (8 KB needed)
    ((float4*)s_av)[(ksub * 2 + 0) * 64 + v4] = a0;
    ((float4*)s_av)[(ksub * 2 + 1) * 64 + v4] = a1;
    __syncthreads();
    if (t < 128) {
        int qq = t >> 6, vv4 = t & 63;
        float4 s = {0, 0, 0, 0};
        #pragma unroll
        for (int ks = 0; ks < 4; ++ks) {
            float4 p = ((const float4*)s_av)[(ks * 2 + qq) * 64 + vv4];
            s.x += p.x; s.y += p.y; s.z += p.z; s.w += p.w;
        }
        float inv = s_inv[qq];
        float4 o = {s.x * inv, s.y * inv, s.z * inv, s.w * inv};
        ((float4*)(out + (size_t)(b * QN + q0 + qq) * DD))[vv4] = o;
    }
}

// ---------------------------------------------------------------------------
extern "C" void kernel_launch(void* const* d_in, const int* in_sizes, int n_in,
                              void* d_out, int out_size)
{
    const float* queries    = (const float*)d_in[0];   // [4,256,256]
    const float* keys       = (const float*)d_in[1];   // [4,1024,256]
    const float* values     = (const float*)d_in[2];   // [4,1024,256]
    const int*   valid_lens = (const int*)  d_in[3];   // [4]
    const float* W_q        = (const float*)d_in[4];   // [128,256]
    const float* W_k        = (const float*)d_in[5];   // [128,256]
    const float* w_v        = (const float*)d_in[6];   // [128]
    float* out = (float*)d_out;                        // [4,256,256]

    proj_kernel<<< (BB * QN) / RPB + (BB * KN) / RPB, 256 >>>(queries, W_q, keys, W_k, valid_lens);
    attn_kernel<<< BB * (QN / 2), 256 >>>(values, valid_lens, w_v, out);
}